// round 13
// baseline (speedup 1.0000x reference)
#include <cuda_runtime.h>

#define CC 64
#define NPIX (512*512)
#define NL 8
#define NBLK 256
#define PXB 1024
#define CH 512
#define MAXV 520
#define SPITCH 72
#define NS_IT 5

// ---------------- global scratch (statics only; no runtime allocations) ----------------
__device__ int   g_bcnt[2][NBLK][NL];
__device__ int   g_boff[2][NBLK][NL];
__device__ int   g_lbase[2][NL];
__device__ int   g_cnt[2][NL];
__device__ float g_sorted[2][NPIX*CC];          // label-sorted features, [pos][64] row-major
__device__ int   g_posmap[NPIX];                // content: orig pixel -> sorted pos
__device__ float g_ysort[NPIX*CC];              // transformed sorted rows
__device__ float g_p2[2][MAXV][CC*CC];          // per-chunk S2 partials
__device__ float g_p1[2][MAXV][CC];
__device__ float g_S1[2][NL][CC];
__device__ float g_S2[2][NL][CC*CC];
__device__ float g_WC[2][NL][CC*CC];            // [0]=cov_c^{-1/2}, [1]=cov_s^{1/2}
__device__ float g_mu[2][NL][CC];
__device__ float g_T[NL][CC*CC];
__device__ float g_beta[NL][CC];
__device__ int   g_valid[NL];

// ---------------- tf32 mma helpers ----------------
__device__ __forceinline__ unsigned f2tf(float f) {
    unsigned r;
    asm("cvt.rna.tf32.f32 %0, %1;" : "=r"(r) : "f"(f));
    return r;
}
__device__ __forceinline__ void mma_tf32(float4& d,
                                         unsigned a0, unsigned a1, unsigned a2, unsigned a3,
                                         unsigned b0, unsigned b1) {
    asm volatile(
        "mma.sync.aligned.m16n8k8.row.col.f32.tf32.tf32.f32 "
        "{%0,%1,%2,%3}, {%4,%5,%6,%7}, {%8,%9}, {%0,%1,%2,%3};"
        : "+f"(d.x), "+f"(d.y), "+f"(d.z), "+f"(d.w)
        : "r"(a0), "r"(a1), "r"(a2), "r"(a3), "r"(b0), "r"(b1));
}

// ================= 1. hist =================
__global__ __launch_bounds__(256, 1)
void hist_kernel(const int* __restrict__ cs, const int* __restrict__ ss) {
    __shared__ int hc[NL];
    int dir = blockIdx.y;
    const int* seg = dir ? ss : cs;
    int b = blockIdx.x, tid = threadIdx.x;
    if (tid < NL) hc[tid] = 0;
    __syncthreads();
    #pragma unroll
    for (int wv = 0; wv < 4; wv++)
        atomicAdd(&hc[seg[b*PXB + wv*256 + tid] & 7], 1);
    __syncthreads();
    if (tid < NL) g_bcnt[dir][b][tid] = hc[tid];
}

// ================= 2. scan =================
__global__ __launch_bounds__(256, 1) void scan_kernel() {
    __shared__ int sc[256];
    __shared__ int tot[16];
    int tid = threadIdx.x;
    for (int pair = 0; pair < 16; pair++) {
        int dir = pair >> 3, l = pair & 7;
        int v = g_bcnt[dir][tid][l];
        sc[tid] = v;
        __syncthreads();
        for (int off = 1; off < 256; off <<= 1) {
            int t = (tid >= off) ? sc[tid - off] : 0;
            __syncthreads();
            sc[tid] += t;
            __syncthreads();
        }
        g_boff[dir][tid][l] = sc[tid] - v;
        if (tid == 255) tot[pair] = sc[255];
        __syncthreads();
    }
    if (tid < 16) {
        int dir = tid >> 3, l = tid & 7;
        int base = 0;
        for (int ll = 0; ll < l; ll++) base += tot[dir*8 + ll];
        g_lbase[dir][l] = base;
        g_cnt[dir][l]   = tot[tid];
    }
}

// ================= 3. scatter: stable counting sort + inverse perm =================
__global__ __launch_bounds__(256, 1)
void scatter_kernel(const float* __restrict__ cf, const float* __restrict__ sf,
                    const int* __restrict__ cs, const int* __restrict__ ss) {
    extern __shared__ float xs[];           // [256][65]
    __shared__ int pos[256];
    __shared__ int wcnt[8][8];
    __shared__ int woff[NL];
    __shared__ int bo[NL];
    int dir = blockIdx.y;
    const float* feat = dir ? sf : cf;
    const int*   seg  = dir ? ss : cs;
    int b = blockIdx.x, tid = threadIdx.x;
    int lane = tid & 31, w = tid >> 5;
    float* dst = &g_sorted[dir][0];
    if (tid < NL) { bo[tid] = g_lbase[dir][tid] + g_boff[dir][b][tid]; woff[tid] = 0; }
    __syncthreads();

    for (int wv = 0; wv < 4; wv++) {
        int p = b*PXB + wv*256 + tid;
        int lab = seg[p] & 7;
        if (tid < 64) wcnt[tid >> 3][tid & 7] = 0;
        __syncthreads();
        unsigned m = __match_any_sync(0xffffffffu, lab);
        int rnk = __popc(m & ((1u << lane) - 1u));
        if (rnk == 0) wcnt[w][lab] = __popc(m);
        __syncthreads();
        int before = woff[lab];
        #pragma unroll
        for (int w2 = 0; w2 < 8; w2++) if (w2 < w) before += wcnt[w2][lab];
        int mypos = bo[lab] + before + rnk;
        pos[tid] = mypos;
        if (dir == 0) g_posmap[p] = mypos;
        #pragma unroll 8
        for (int c = 0; c < CC; c++)
            xs[tid*65 + c] = feat[c*NPIX + p];
        __syncthreads();
        if (tid < NL) {
            int t = 0;
            #pragma unroll
            for (int w2 = 0; w2 < 8; w2++) t += wcnt[w2][tid];
            woff[tid] += t;
        }
        for (int k = tid; k < 256*CC; k += 256) {
            int px = k >> 6, c = k & 63;
            dst[pos[px]*CC + c] = xs[px*65 + c];
        }
        __syncthreads();
    }
}

// ================= 4. stats: tf32 tensor-core SYRK per chunk =================
__global__ __launch_bounds__(256, 2) void stats_kernel() {
    __shared__ unsigned xs[128*SPITCH];
    __shared__ int cb[NL+1], kb[NL];
    __shared__ int sl, sks, ske;
    __shared__ float s1p[4][CC];
    int dir = blockIdx.y, v = blockIdx.x, tid = threadIdx.x;
    if (tid == 0) {
        int c = 0, k = 0;
        for (int l = 0; l < NL; l++) {
            int n = g_cnt[dir][l];
            kb[l] = k; cb[l] = c;
            c += (n + CH - 1) / CH; k += n;
        }
        cb[NL] = c;
        if (v < c) {
            int l = 0;
            while (cb[l+1] <= v) l++;
            int ks = kb[l] + (v - cb[l]) * CH;
            int ke = kb[l] + g_cnt[dir][l];
            if (ke > ks + CH) ke = ks + CH;
            sl = l; sks = ks; ske = ke;
        } else sl = -1;
    }
    __syncthreads();
    if (sl < 0) return;
    int ks = sks, ke = ske;

    int w = tid >> 5, lane = tid & 31;
    int g = lane >> 2, t = lane & 3;
    int rowbase = (w & 3) * 16, colbase = (w >> 2) * 32;
    int t64 = tid & 63, g1 = tid >> 6;

    float4 dacc[4];
    #pragma unroll
    for (int j = 0; j < 4; j++) dacc[j] = make_float4(0.f, 0.f, 0.f, 0.f);
    float s1r = 0.f;
    const float* src = &g_sorted[dir][0];

    for (int kt = ks; kt < ke; kt += 128) {
        __syncthreads();
        // stage + tf32-round, zero-pad past label end
        for (int k = tid; k < 128*CC; k += 256) {
            int r = k >> 6, c = k & 63;
            float f = (kt + r < ke) ? src[(kt + r)*CC + c] : 0.f;
            xs[r*SPITCH + c] = f2tf(f);
        }
        __syncthreads();
        // S1 ride-along (zeros contribute nothing)
        #pragma unroll 4
        for (int j = g1; j < 128; j += 4) s1r += __uint_as_float(xs[j*SPITCH + t64]);
        // tensor SYRK: 16 k-steps of 8 pixels
        #pragma unroll
        for (int kk = 0; kk < 128; kk += 8) {
            unsigned a0 = xs[(kk + t    )*SPITCH + rowbase + g];
            unsigned a1 = xs[(kk + t    )*SPITCH + rowbase + g + 8];
            unsigned a2 = xs[(kk + t + 4)*SPITCH + rowbase + g];
            unsigned a3 = xs[(kk + t + 4)*SPITCH + rowbase + g + 8];
            #pragma unroll
            for (int j = 0; j < 4; j++) {
                unsigned b0 = xs[(kk + t    )*SPITCH + colbase + j*8 + g];
                unsigned b1 = xs[(kk + t + 4)*SPITCH + colbase + j*8 + g];
                mma_tf32(dacc[j], a0, a1, a2, a3, b0, b1);
            }
        }
    }
    // write C partials: warp owns 16x32 slab, thread holds (g,2t) pairs
    float* P = &g_p2[dir][v][0];
    #pragma unroll
    for (int j = 0; j < 4; j++) {
        int col = colbase + j*8 + 2*t;
        *(float2*)&P[(rowbase + g    )*CC + col] = make_float2(dacc[j].x, dacc[j].y);
        *(float2*)&P[(rowbase + g + 8)*CC + col] = make_float2(dacc[j].z, dacc[j].w);
    }
    s1p[g1][t64] = s1r;
    __syncthreads();
    if (tid < CC)
        g_p1[dir][v][tid] = s1p[0][tid] + s1p[1][tid] + s1p[2][tid] + s1p[3][tid];
}

// ================= 5. reduce =================
__global__ __launch_bounds__(256, 1) void reduce_kernel() {
    __shared__ int rs, re;
    int dir = blockIdx.x >> 3, l = blockIdx.x & 7, tid = threadIdx.x;
    int slice = blockIdx.y;                  // 4 slices of 1024 elems
    if (tid == 0) {
        int c = 0, cs0 = 0, n0 = 0;
        for (int ll = 0; ll < NL; ll++) {
            int n = g_cnt[dir][ll];
            int nc = (n + CH - 1) / CH;
            if (ll == l) { cs0 = c; n0 = nc; }
            c += nc;
        }
        rs = cs0; re = cs0 + n0;
    }
    __syncthreads();
    int a = rs, b = re;
    for (int e = slice*1024 + tid; e < slice*1024 + 1024; e += 256) {
        float s = 0.f;
        for (int v = a; v < b; v++) s += g_p2[dir][v][e];
        g_S2[dir][l][e] = s;
    }
    if (slice == 0 && tid < CC) {
        float s = 0.f;
        for (int v = a; v < b; v++) s += g_p1[dir][v][tid];
        g_S1[dir][l][tid] = s;
    }
}

// ---------------- 64x64x64 in-block matmul, 256 threads ----------------
__device__ __forceinline__ void mm64(float* __restrict__ C,
                                     const float* __restrict__ A,
                                     const float* __restrict__ B,
                                     int tid, int nsform) {
    int rr = tid >> 4, cr = tid & 15;
    float acc[4][4] = {};
    #pragma unroll 4
    for (int k = 0; k < 64; k += 4) {
        float4 a[4], b[4];
        #pragma unroll
        for (int r = 0; r < 4; r++) a[r] = *(const float4*)&A[(rr*4 + r)*64 + k];
        #pragma unroll
        for (int i = 0; i < 4; i++) b[i] = *(const float4*)&B[(k + i)*64 + cr*4];
        #pragma unroll
        for (int r = 0; r < 4; r++) {
            float4 ar = a[r];
            acc[r][0] += ar.x*b[0].x + ar.y*b[1].x + ar.z*b[2].x + ar.w*b[3].x;
            acc[r][1] += ar.x*b[0].y + ar.y*b[1].y + ar.z*b[2].y + ar.w*b[3].y;
            acc[r][2] += ar.x*b[0].z + ar.y*b[1].z + ar.z*b[2].z + ar.w*b[3].z;
            acc[r][3] += ar.x*b[0].w + ar.y*b[1].w + ar.z*b[2].w + ar.w*b[3].w;
        }
    }
    #pragma unroll
    for (int r = 0; r < 4; r++)
        #pragma unroll
        for (int c = 0; c < 4; c++) {
            float v = acc[r][c];
            if (nsform) v = ((rr*4 + r) == (cr*4 + c) ? 1.5f : 0.f) - 0.5f*v;
            C[(rr*4 + r)*64 + cr*4 + c] = v;
        }
}

// ============ 6. Newton-Schulz ============
__global__ __launch_bounds__(256, 1) void ns_kernel() {
    extern __shared__ float sm[];
    float *Yp = sm, *Zp = sm + 4096, *Wp = sm + 8192, *Vp = sm + 12288;
    int lab = blockIdx.x >> 1, which = blockIdx.x & 1;
    int tid = threadIdx.x;
    __shared__ float mu[CC], rowsum[CC], s_sh;

    int n = g_cnt[which][lab];
    float fn = (float)n;
    if (tid < CC) mu[tid] = g_S1[which][lab][tid] / fmaxf(fn, 1.f);
    __syncthreads();
    float div = (fn - 1.f == 0.f) ? 1e-5f : (fn - 1.f);
    for (int k = tid; k < 4096; k += 256) {
        int i = k >> 6, j = k & 63;
        float a = (g_S2[which][lab][k] - fn*mu[i]*mu[j]) / div;
        if (which == 0 && i == j) a += 1.f;
        Yp[k] = a;
    }
    __syncthreads();
    if (n <= 10) {
        for (int k = tid; k < 4096; k += 256)
            g_WC[which][lab][k] = ((k >> 6) == (k & 63)) ? 1.f : 0.f;
        if (tid < CC) g_mu[which][lab][tid] = mu[tid];
        return;
    }
    if (tid < CC) {
        float sr = 0.f;
        for (int j = 0; j < 64; j++) sr += fabsf(Yp[tid*64 + j]);
        rowsum[tid] = sr;
    }
    __syncthreads();
    if (tid == 0) {
        float m = 1e-10f;
        for (int i = 0; i < CC; i++) m = fmaxf(m, rowsum[i]);
        s_sh = m;
    }
    __syncthreads();
    float s = s_sh, inv_s = 1.f / s;
    for (int k = tid; k < 4096; k += 256) {
        Yp[k] *= inv_s;
        Zp[k] = ((k >> 6) == (k & 63)) ? 1.f : 0.f;
    }
    __syncthreads();
    for (int it = 0; it < NS_IT; it++) {
        mm64(Wp, Zp, Yp, tid, 1);
        __syncthreads();
        mm64(Vp, Yp, Wp, tid, 0);
        __syncthreads();
        mm64(Yp, Wp, Zp, tid, 0);
        __syncthreads();
        float* t = Yp; Yp = Vp; Vp = Zp; Zp = t;
    }
    float fac = (which == 0) ? rsqrtf(s) : sqrtf(s);
    const float* srcm = (which == 0) ? Zp : Yp;
    for (int k = tid; k < 4096; k += 256) g_WC[which][lab][k] = srcm[k] * fac;
    if (tid < CC) g_mu[which][lab][tid] = mu[tid];
}

// ============ 7. combine ============
__global__ __launch_bounds__(256, 1) void combine_kernel() {
    extern __shared__ float csm[];
    float* Co = csm; float* Wh = csm + 4096; float* Tt = csm + 8192;
    int lab = blockIdx.x, tid = threadIdx.x;
    for (int k = tid; k < 4096; k += 256) {
        Co[k] = g_WC[1][lab][k];
        Wh[k] = g_WC[0][lab][k];
    }
    __syncthreads();
    mm64(Tt, Co, Wh, tid, 0);
    __syncthreads();
    for (int k = tid; k < 4096; k += 256) g_T[lab][k] = Tt[k];
    if (tid < CC) {
        float b = g_mu[1][lab][tid];
        const float* Tr = &Tt[tid*64];
        #pragma unroll 8
        for (int q = 0; q < CC; q++) b -= Tr[q] * g_mu[0][lab][q];
        g_beta[lab][tid] = b;
    }
    if (tid == 0) {
        float nc = (float)g_cnt[0][lab], ns = (float)g_cnt[1][lab];
        g_valid[lab] = (nc > 10.f) && (ns > 10.f) && (nc < 100.f*ns) && (ns < 100.f*nc);
    }
}

// ============ 8. apply on sorted rows: ysort = T x + beta (or x if invalid) ============
__global__ __launch_bounds__(256, 2) void apply_kernel() {
    extern __shared__ float asmem[];
    float* T0 = asmem;            // 4096
    float* T1 = asmem + 4096;     // 4096
    __shared__ int lb[NL];
    __shared__ float bet[2][CC];
    __shared__ int labA, labB, vA, vB;
    int tid = threadIdx.x;
    int pos0 = blockIdx.x * 256;
    if (tid < NL) lb[tid] = g_lbase[0][tid];
    __syncthreads();
    if (tid == 0) {
        int la = 0, lz = 0;
        #pragma unroll
        for (int ll = 1; ll < NL; ll++) {
            if (pos0       >= lb[ll]) la = ll;
            if (pos0 + 255 >= lb[ll]) lz = ll;
        }
        labA = la; labB = lz;
        vA = g_valid[la]; vB = g_valid[lz];
    }
    __syncthreads();
    int la = labA, lz = labB;
    for (int k = tid; k < 4096; k += 256) T0[k] = g_T[la][k];
    if (lz != la)
        for (int k = tid; k < 4096; k += 256) T1[k] = g_T[lz][k];
    if (tid < CC) {
        bet[0][tid] = g_beta[la][tid];
        bet[1][tid] = g_beta[lz][tid];
    }
    __syncthreads();

    int pos = pos0 + tid;
    int l = 0;
    #pragma unroll
    for (int ll = 1; ll < NL; ll++) if (pos >= lb[ll]) l = ll;

    const float* xr = &g_sorted[0][(long)pos*CC];
    float x[CC];
    #pragma unroll
    for (int i = 0; i < 16; i++) {
        float4 v = *(const float4*)&xr[i*4];
        x[i*4] = v.x; x[i*4+1] = v.y; x[i*4+2] = v.z; x[i*4+3] = v.w;
    }
    float* yr = &g_ysort[(long)pos*CC];
    int sel = (l == la) ? 0 : 1;
    int valid = sel ? vB : vA;
    if (!valid) {
        #pragma unroll
        for (int i = 0; i < 16; i++)
            *(float4*)&yr[i*4] = *(const float4*)&xr[i*4];
        return;
    }
    const float* T  = sel ? T1 : T0;
    const float* bl = bet[sel];
    for (int c0 = 0; c0 < CC; c0 += 4) {
        float a0 = bl[c0], a1 = bl[c0+1], a2 = bl[c0+2], a3 = bl[c0+3];
        #pragma unroll
        for (int q = 0; q < CC; q += 4) {
            float4 t0 = *(const float4*)&T[(c0+0)*64 + q];
            float4 t1 = *(const float4*)&T[(c0+1)*64 + q];
            float4 t2 = *(const float4*)&T[(c0+2)*64 + q];
            float4 t3 = *(const float4*)&T[(c0+3)*64 + q];
            a0 += t0.x*x[q] + t0.y*x[q+1] + t0.z*x[q+2] + t0.w*x[q+3];
            a1 += t1.x*x[q] + t1.y*x[q+1] + t1.z*x[q+2] + t1.w*x[q+3];
            a2 += t2.x*x[q] + t2.y*x[q+1] + t2.z*x[q+2] + t2.w*x[q+3];
            a3 += t3.x*x[q] + t3.y*x[q+1] + t3.z*x[q+2] + t3.w*x[q+3];
        }
        *(float4*)&yr[c0] = make_float4(a0, a1, a2, a3);
    }
}

// ============ 9. writeout: gather sorted rows back to channel-major ============
__global__ __launch_bounds__(256, 2) void writeout_kernel(float* __restrict__ out) {
    int p = blockIdx.x*256 + threadIdx.x;
    int pos = g_posmap[p];
    const float* yr = &g_ysort[(long)pos*CC];
    float y[CC];
    #pragma unroll
    for (int i = 0; i < 16; i++) {
        float4 v = *(const float4*)&yr[i*4];
        y[i*4] = v.x; y[i*4+1] = v.y; y[i*4+2] = v.z; y[i*4+3] = v.w;
    }
    #pragma unroll
    for (int c = 0; c < CC; c++) out[c*NPIX + p] = y[c];
}

extern "C" void kernel_launch(void* const* d_in, const int* in_sizes, int n_in,
                              void* d_out, int out_size) {
    const float* cf = (const float*)d_in[0];
    const float* sf = (const float*)d_in[1];
    const int*   cs = (const int*)d_in[2];
    const int*   ss = (const int*)d_in[3];
    float* out = (float*)d_out;

    int scat_smem  = 256*65*4;      // 66560
    int ns_smem    = 4*4096*4;      // 65536
    int comb_smem  = 3*4096*4;      // 49152
    int apply_smem = 2*4096*4;      // 32768

    cudaFuncSetAttribute(scatter_kernel, cudaFuncAttributeMaxDynamicSharedMemorySize, scat_smem);
    cudaFuncSetAttribute(ns_kernel,      cudaFuncAttributeMaxDynamicSharedMemorySize, ns_smem);
    cudaFuncSetAttribute(combine_kernel, cudaFuncAttributeMaxDynamicSharedMemorySize, comb_smem);
    cudaFuncSetAttribute(apply_kernel,   cudaFuncAttributeMaxDynamicSharedMemorySize, apply_smem);

    hist_kernel<<<dim3(NBLK, 2), 256>>>(cs, ss);                        // 1
    scan_kernel<<<1, 256>>>();                                          // 2
    scatter_kernel<<<dim3(NBLK, 2), 256, scat_smem>>>(cf, sf, cs, ss);  // 3
    stats_kernel<<<dim3(MAXV, 2), 256>>>();                             // 4 (profiled)
    reduce_kernel<<<dim3(16, 4), 256>>>();                              // 5
    ns_kernel<<<16, 256, ns_smem>>>();                                  // 6
    combine_kernel<<<NL, 256, comb_smem>>>();                           // 7
    apply_kernel<<<NPIX/256, 256, apply_smem>>>();                      // 8
    writeout_kernel<<<NPIX/256, 256>>>(out);                            // 9
}

// round 14
// speedup vs baseline: 1.0047x; 1.0047x over previous
#include <cuda_runtime.h>

#define CC 64
#define NPIX (512*512)
#define NL 8
#define NBLK 256
#define PXB 1024
#define CH 512
#define MAXV 520
#define SPITCH 72
#define NS_IT 5

// ---------------- global scratch (statics only; no runtime allocations) ----------------
__device__ int   g_bcnt[2][NBLK][NL];
__device__ int   g_boff[2][NBLK][NL];
__device__ int   g_lbase[2][NL];
__device__ int   g_cnt[2][NL];
__device__ float g_sorted[2][NPIX*CC];          // label-sorted features, [pos][64] row-major
__device__ int   g_posmap[NPIX];                // content: orig pixel -> sorted pos
__device__ float g_ysort[NPIX*CC];              // transformed sorted rows
__device__ float g_p2[2][MAXV][CC*CC];          // per-chunk S2 partials
__device__ float g_p1[2][MAXV][CC];
__device__ float g_S1[2][NL][CC];
__device__ float g_S2[2][NL][CC*CC];
__device__ float g_WC[2][NL][CC*CC];            // [0]=cov_c^{-1/2}, [1]=cov_s^{1/2}
__device__ float g_mu[2][NL][CC];
__device__ float g_T[NL][CC*CC];
__device__ float g_beta[NL][CC];
__device__ int   g_valid[NL];

// ---------------- tf32 mma helpers ----------------
__device__ __forceinline__ unsigned f2tf(float f) {
    unsigned r;
    asm("cvt.rna.tf32.f32 %0, %1;" : "=r"(r) : "f"(f));
    return r;
}
__device__ __forceinline__ void mma_tf32(float4& d,
                                         unsigned a0, unsigned a1, unsigned a2, unsigned a3,
                                         unsigned b0, unsigned b1) {
    asm volatile(
        "mma.sync.aligned.m16n8k8.row.col.f32.tf32.tf32.f32 "
        "{%0,%1,%2,%3}, {%4,%5,%6,%7}, {%8,%9}, {%0,%1,%2,%3};"
        : "+f"(d.x), "+f"(d.y), "+f"(d.z), "+f"(d.w)
        : "r"(a0), "r"(a1), "r"(a2), "r"(a3), "r"(b0), "r"(b1));
}

// ================= 1. hist =================
__global__ __launch_bounds__(256, 1)
void hist_kernel(const int* __restrict__ cs, const int* __restrict__ ss) {
    __shared__ int hc[NL];
    int dir = blockIdx.y;
    const int* seg = dir ? ss : cs;
    int b = blockIdx.x, tid = threadIdx.x;
    if (tid < NL) hc[tid] = 0;
    __syncthreads();
    #pragma unroll
    for (int wv = 0; wv < 4; wv++)
        atomicAdd(&hc[seg[b*PXB + wv*256 + tid] & 7], 1);
    __syncthreads();
    if (tid < NL) g_bcnt[dir][b][tid] = hc[tid];
}

// ================= 2. scan =================
__global__ __launch_bounds__(256, 1) void scan_kernel() {
    __shared__ int sc[256];
    __shared__ int tot[16];
    int tid = threadIdx.x;
    for (int pair = 0; pair < 16; pair++) {
        int dir = pair >> 3, l = pair & 7;
        int v = g_bcnt[dir][tid][l];
        sc[tid] = v;
        __syncthreads();
        for (int off = 1; off < 256; off <<= 1) {
            int t = (tid >= off) ? sc[tid - off] : 0;
            __syncthreads();
            sc[tid] += t;
            __syncthreads();
        }
        g_boff[dir][tid][l] = sc[tid] - v;
        if (tid == 255) tot[pair] = sc[255];
        __syncthreads();
    }
    if (tid < 16) {
        int dir = tid >> 3, l = tid & 7;
        int base = 0;
        for (int ll = 0; ll < l; ll++) base += tot[dir*8 + ll];
        g_lbase[dir][l] = base;
        g_cnt[dir][l]   = tot[tid];
    }
}

// ================= 3. scatter: stable counting sort + inverse perm =================
__global__ __launch_bounds__(256, 1)
void scatter_kernel(const float* __restrict__ cf, const float* __restrict__ sf,
                    const int* __restrict__ cs, const int* __restrict__ ss) {
    extern __shared__ float xs[];           // [256][65]
    __shared__ int pos[256];
    __shared__ int wcnt[8][8];
    __shared__ int woff[NL];
    __shared__ int bo[NL];
    int dir = blockIdx.y;
    const float* feat = dir ? sf : cf;
    const int*   seg  = dir ? ss : cs;
    int b = blockIdx.x, tid = threadIdx.x;
    int lane = tid & 31, w = tid >> 5;
    float* dst = &g_sorted[dir][0];
    if (tid < NL) { bo[tid] = g_lbase[dir][tid] + g_boff[dir][b][tid]; woff[tid] = 0; }
    __syncthreads();

    for (int wv = 0; wv < 4; wv++) {
        int p = b*PXB + wv*256 + tid;
        int lab = seg[p] & 7;
        if (tid < 64) wcnt[tid >> 3][tid & 7] = 0;
        __syncthreads();
        unsigned m = __match_any_sync(0xffffffffu, lab);
        int rnk = __popc(m & ((1u << lane) - 1u));
        if (rnk == 0) wcnt[w][lab] = __popc(m);
        __syncthreads();
        int before = woff[lab];
        #pragma unroll
        for (int w2 = 0; w2 < 8; w2++) if (w2 < w) before += wcnt[w2][lab];
        int mypos = bo[lab] + before + rnk;
        pos[tid] = mypos;
        if (dir == 0) g_posmap[p] = mypos;
        #pragma unroll 8
        for (int c = 0; c < CC; c++)
            xs[tid*65 + c] = feat[c*NPIX + p];
        __syncthreads();
        if (tid < NL) {
            int t = 0;
            #pragma unroll
            for (int w2 = 0; w2 < 8; w2++) t += wcnt[w2][tid];
            woff[tid] += t;
        }
        for (int k = tid; k < 256*CC; k += 256) {
            int px = k >> 6, c = k & 63;
            dst[pos[px]*CC + c] = xs[px*65 + c];
        }
        __syncthreads();
    }
}

// ================= 4. stats: tf32 tensor-core SYRK per chunk =================
__global__ __launch_bounds__(256, 2) void stats_kernel() {
    __shared__ unsigned xs[128*SPITCH];
    __shared__ int cb[NL+1], kb[NL];
    __shared__ int sl, sks, ske;
    __shared__ float s1p[4][CC];
    int dir = blockIdx.y, v = blockIdx.x, tid = threadIdx.x;
    if (tid == 0) {
        int c = 0, k = 0;
        for (int l = 0; l < NL; l++) {
            int n = g_cnt[dir][l];
            kb[l] = k; cb[l] = c;
            c += (n + CH - 1) / CH; k += n;
        }
        cb[NL] = c;
        if (v < c) {
            int l = 0;
            while (cb[l+1] <= v) l++;
            int ks = kb[l] + (v - cb[l]) * CH;
            int ke = kb[l] + g_cnt[dir][l];
            if (ke > ks + CH) ke = ks + CH;
            sl = l; sks = ks; ske = ke;
        } else sl = -1;
    }
    __syncthreads();
    if (sl < 0) return;
    int ks = sks, ke = ske;

    int w = tid >> 5, lane = tid & 31;
    int g = lane >> 2, t = lane & 3;
    int rowbase = (w & 3) * 16, colbase = (w >> 2) * 32;
    int t64 = tid & 63, g1 = tid >> 6;

    float4 dacc[4];
    #pragma unroll
    for (int j = 0; j < 4; j++) dacc[j] = make_float4(0.f, 0.f, 0.f, 0.f);
    float s1r = 0.f;
    const float* src = &g_sorted[dir][0];

    for (int kt = ks; kt < ke; kt += 128) {
        __syncthreads();
        // stage + tf32-round, zero-pad past label end
        for (int k = tid; k < 128*CC; k += 256) {
            int r = k >> 6, c = k & 63;
            float f = (kt + r < ke) ? src[(kt + r)*CC + c] : 0.f;
            xs[r*SPITCH + c] = f2tf(f);
        }
        __syncthreads();
        // S1 ride-along (zeros contribute nothing)
        #pragma unroll 4
        for (int j = g1; j < 128; j += 4) s1r += __uint_as_float(xs[j*SPITCH + t64]);
        // tensor SYRK: 16 k-steps of 8 pixels
        #pragma unroll
        for (int kk = 0; kk < 128; kk += 8) {
            unsigned a0 = xs[(kk + t    )*SPITCH + rowbase + g];
            unsigned a1 = xs[(kk + t    )*SPITCH + rowbase + g + 8];
            unsigned a2 = xs[(kk + t + 4)*SPITCH + rowbase + g];
            unsigned a3 = xs[(kk + t + 4)*SPITCH + rowbase + g + 8];
            #pragma unroll
            for (int j = 0; j < 4; j++) {
                unsigned b0 = xs[(kk + t    )*SPITCH + colbase + j*8 + g];
                unsigned b1 = xs[(kk + t + 4)*SPITCH + colbase + j*8 + g];
                mma_tf32(dacc[j], a0, a1, a2, a3, b0, b1);
            }
        }
    }
    // write C partials: warp owns 16x32 slab, thread holds (g,2t) pairs
    float* P = &g_p2[dir][v][0];
    #pragma unroll
    for (int j = 0; j < 4; j++) {
        int col = colbase + j*8 + 2*t;
        *(float2*)&P[(rowbase + g    )*CC + col] = make_float2(dacc[j].x, dacc[j].y);
        *(float2*)&P[(rowbase + g + 8)*CC + col] = make_float2(dacc[j].z, dacc[j].w);
    }
    s1p[g1][t64] = s1r;
    __syncthreads();
    if (tid < CC)
        g_p1[dir][v][tid] = s1p[0][tid] + s1p[1][tid] + s1p[2][tid] + s1p[3][tid];
}

// ================= 5. reduce =================
__global__ __launch_bounds__(256, 1) void reduce_kernel() {
    __shared__ int rs, re;
    int dir = blockIdx.x >> 3, l = blockIdx.x & 7, tid = threadIdx.x;
    int slice = blockIdx.y;                  // 4 slices of 1024 elems
    if (tid == 0) {
        int c = 0, cs0 = 0, n0 = 0;
        for (int ll = 0; ll < NL; ll++) {
            int n = g_cnt[dir][ll];
            int nc = (n + CH - 1) / CH;
            if (ll == l) { cs0 = c; n0 = nc; }
            c += nc;
        }
        rs = cs0; re = cs0 + n0;
    }
    __syncthreads();
    int a = rs, b = re;
    for (int e = slice*1024 + tid; e < slice*1024 + 1024; e += 256) {
        float s = 0.f;
        for (int v = a; v < b; v++) s += g_p2[dir][v][e];
        g_S2[dir][l][e] = s;
    }
    if (slice == 0 && tid < CC) {
        float s = 0.f;
        for (int v = a; v < b; v++) s += g_p1[dir][v][tid];
        g_S1[dir][l][tid] = s;
    }
}

// ---------------- 64x64x64 in-block matmul, 256 threads ----------------
__device__ __forceinline__ void mm64(float* __restrict__ C,
                                     const float* __restrict__ A,
                                     const float* __restrict__ B,
                                     int tid, int nsform) {
    int rr = tid >> 4, cr = tid & 15;
    float acc[4][4] = {};
    #pragma unroll 4
    for (int k = 0; k < 64; k += 4) {
        float4 a[4], b[4];
        #pragma unroll
        for (int r = 0; r < 4; r++) a[r] = *(const float4*)&A[(rr*4 + r)*64 + k];
        #pragma unroll
        for (int i = 0; i < 4; i++) b[i] = *(const float4*)&B[(k + i)*64 + cr*4];
        #pragma unroll
        for (int r = 0; r < 4; r++) {
            float4 ar = a[r];
            acc[r][0] += ar.x*b[0].x + ar.y*b[1].x + ar.z*b[2].x + ar.w*b[3].x;
            acc[r][1] += ar.x*b[0].y + ar.y*b[1].y + ar.z*b[2].y + ar.w*b[3].y;
            acc[r][2] += ar.x*b[0].z + ar.y*b[1].z + ar.z*b[2].z + ar.w*b[3].z;
            acc[r][3] += ar.x*b[0].w + ar.y*b[1].w + ar.z*b[2].w + ar.w*b[3].w;
        }
    }
    #pragma unroll
    for (int r = 0; r < 4; r++)
        #pragma unroll
        for (int c = 0; c < 4; c++) {
            float v = acc[r][c];
            if (nsform) v = ((rr*4 + r) == (cr*4 + c) ? 1.5f : 0.f) - 0.5f*v;
            C[(rr*4 + r)*64 + cr*4 + c] = v;
        }
}

// ============ 6. Newton-Schulz ============
__global__ __launch_bounds__(256, 1) void ns_kernel() {
    extern __shared__ float sm[];
    float *Yp = sm, *Zp = sm + 4096, *Wp = sm + 8192, *Vp = sm + 12288;
    int lab = blockIdx.x >> 1, which = blockIdx.x & 1;
    int tid = threadIdx.x;
    __shared__ float mu[CC], rowsum[CC], s_sh;

    int n = g_cnt[which][lab];
    float fn = (float)n;
    if (tid < CC) mu[tid] = g_S1[which][lab][tid] / fmaxf(fn, 1.f);
    __syncthreads();
    float div = (fn - 1.f == 0.f) ? 1e-5f : (fn - 1.f);
    for (int k = tid; k < 4096; k += 256) {
        int i = k >> 6, j = k & 63;
        float a = (g_S2[which][lab][k] - fn*mu[i]*mu[j]) / div;
        if (which == 0 && i == j) a += 1.f;
        Yp[k] = a;
    }
    __syncthreads();
    if (n <= 10) {
        for (int k = tid; k < 4096; k += 256)
            g_WC[which][lab][k] = ((k >> 6) == (k & 63)) ? 1.f : 0.f;
        if (tid < CC) g_mu[which][lab][tid] = mu[tid];
        return;
    }
    if (tid < CC) {
        float sr = 0.f;
        for (int j = 0; j < 64; j++) sr += fabsf(Yp[tid*64 + j]);
        rowsum[tid] = sr;
    }
    __syncthreads();
    if (tid == 0) {
        float m = 1e-10f;
        for (int i = 0; i < CC; i++) m = fmaxf(m, rowsum[i]);
        s_sh = m;
    }
    __syncthreads();
    float s = s_sh, inv_s = 1.f / s;
    for (int k = tid; k < 4096; k += 256) {
        Yp[k] *= inv_s;
        Zp[k] = ((k >> 6) == (k & 63)) ? 1.f : 0.f;
    }
    __syncthreads();
    for (int it = 0; it < NS_IT; it++) {
        mm64(Wp, Zp, Yp, tid, 1);
        __syncthreads();
        mm64(Vp, Yp, Wp, tid, 0);
        __syncthreads();
        mm64(Yp, Wp, Zp, tid, 0);
        __syncthreads();
        float* t = Yp; Yp = Vp; Vp = Zp; Zp = t;
    }
    float fac = (which == 0) ? rsqrtf(s) : sqrtf(s);
    const float* srcm = (which == 0) ? Zp : Yp;
    for (int k = tid; k < 4096; k += 256) g_WC[which][lab][k] = srcm[k] * fac;
    if (tid < CC) g_mu[which][lab][tid] = mu[tid];
}

// ============ 7. combine ============
__global__ __launch_bounds__(256, 1) void combine_kernel() {
    extern __shared__ float csm[];
    float* Co = csm; float* Wh = csm + 4096; float* Tt = csm + 8192;
    int lab = blockIdx.x, tid = threadIdx.x;
    for (int k = tid; k < 4096; k += 256) {
        Co[k] = g_WC[1][lab][k];
        Wh[k] = g_WC[0][lab][k];
    }
    __syncthreads();
    mm64(Tt, Co, Wh, tid, 0);
    __syncthreads();
    for (int k = tid; k < 4096; k += 256) g_T[lab][k] = Tt[k];
    if (tid < CC) {
        float b = g_mu[1][lab][tid];
        const float* Tr = &Tt[tid*64];
        #pragma unroll 8
        for (int q = 0; q < CC; q++) b -= Tr[q] * g_mu[0][lab][q];
        g_beta[lab][tid] = b;
    }
    if (tid == 0) {
        float nc = (float)g_cnt[0][lab], ns = (float)g_cnt[1][lab];
        g_valid[lab] = (nc > 10.f) && (ns > 10.f) && (nc < 100.f*ns) && (ns < 100.f*nc);
    }
}

// ============ 8. apply on sorted rows: ysort = T x + beta (or x if invalid) ============
__global__ __launch_bounds__(256, 2) void apply_kernel() {
    extern __shared__ float asmem[];
    float* T0 = asmem;            // 4096
    float* T1 = asmem + 4096;     // 4096
    __shared__ int lb[NL];
    __shared__ float bet[2][CC];
    __shared__ int labA, labB, vA, vB;
    int tid = threadIdx.x;
    int pos0 = blockIdx.x * 256;
    if (tid < NL) lb[tid] = g_lbase[0][tid];
    __syncthreads();
    if (tid == 0) {
        int la = 0, lz = 0;
        #pragma unroll
        for (int ll = 1; ll < NL; ll++) {
            if (pos0       >= lb[ll]) la = ll;
            if (pos0 + 255 >= lb[ll]) lz = ll;
        }
        labA = la; labB = lz;
        vA = g_valid[la]; vB = g_valid[lz];
    }
    __syncthreads();
    int la = labA, lz = labB;
    for (int k = tid; k < 4096; k += 256) T0[k] = g_T[la][k];
    if (lz != la)
        for (int k = tid; k < 4096; k += 256) T1[k] = g_T[lz][k];
    if (tid < CC) {
        bet[0][tid] = g_beta[la][tid];
        bet[1][tid] = g_beta[lz][tid];
    }
    __syncthreads();

    int pos = pos0 + tid;
    int l = 0;
    #pragma unroll
    for (int ll = 1; ll < NL; ll++) if (pos >= lb[ll]) l = ll;

    const float* xr = &g_sorted[0][(long)pos*CC];
    float x[CC];
    #pragma unroll
    for (int i = 0; i < 16; i++) {
        float4 v = *(const float4*)&xr[i*4];
        x[i*4] = v.x; x[i*4+1] = v.y; x[i*4+2] = v.z; x[i*4+3] = v.w;
    }
    float* yr = &g_ysort[(long)pos*CC];
    int sel = (l == la) ? 0 : 1;
    int valid = sel ? vB : vA;
    if (!valid) {
        #pragma unroll
        for (int i = 0; i < 16; i++)
            *(float4*)&yr[i*4] = *(const float4*)&xr[i*4];
        return;
    }
    const float* T  = sel ? T1 : T0;
    const float* bl = bet[sel];
    for (int c0 = 0; c0 < CC; c0 += 4) {
        float a0 = bl[c0], a1 = bl[c0+1], a2 = bl[c0+2], a3 = bl[c0+3];
        #pragma unroll
        for (int q = 0; q < CC; q += 4) {
            float4 t0 = *(const float4*)&T[(c0+0)*64 + q];
            float4 t1 = *(const float4*)&T[(c0+1)*64 + q];
            float4 t2 = *(const float4*)&T[(c0+2)*64 + q];
            float4 t3 = *(const float4*)&T[(c0+3)*64 + q];
            a0 += t0.x*x[q] + t0.y*x[q+1] + t0.z*x[q+2] + t0.w*x[q+3];
            a1 += t1.x*x[q] + t1.y*x[q+1] + t1.z*x[q+2] + t1.w*x[q+3];
            a2 += t2.x*x[q] + t2.y*x[q+1] + t2.z*x[q+2] + t2.w*x[q+3];
            a3 += t3.x*x[q] + t3.y*x[q+1] + t3.z*x[q+2] + t3.w*x[q+3];
        }
        *(float4*)&yr[c0] = make_float4(a0, a1, a2, a3);
    }
}

// ============ 9. writeout: gather sorted rows back to channel-major ============
__global__ __launch_bounds__(256, 2) void writeout_kernel(float* __restrict__ out) {
    int p = blockIdx.x*256 + threadIdx.x;
    int pos = g_posmap[p];
    const float* yr = &g_ysort[(long)pos*CC];
    float y[CC];
    #pragma unroll
    for (int i = 0; i < 16; i++) {
        float4 v = *(const float4*)&yr[i*4];
        y[i*4] = v.x; y[i*4+1] = v.y; y[i*4+2] = v.z; y[i*4+3] = v.w;
    }
    #pragma unroll
    for (int c = 0; c < CC; c++) out[c*NPIX + p] = y[c];
}

extern "C" void kernel_launch(void* const* d_in, const int* in_sizes, int n_in,
                              void* d_out, int out_size) {
    const float* cf = (const float*)d_in[0];
    const float* sf = (const float*)d_in[1];
    const int*   cs = (const int*)d_in[2];
    const int*   ss = (const int*)d_in[3];
    float* out = (float*)d_out;

    int scat_smem  = 256*65*4;      // 66560
    int ns_smem    = 4*4096*4;      // 65536
    int comb_smem  = 3*4096*4;      // 49152
    int apply_smem = 2*4096*4;      // 32768

    cudaFuncSetAttribute(scatter_kernel, cudaFuncAttributeMaxDynamicSharedMemorySize, scat_smem);
    cudaFuncSetAttribute(ns_kernel,      cudaFuncAttributeMaxDynamicSharedMemorySize, ns_smem);
    cudaFuncSetAttribute(combine_kernel, cudaFuncAttributeMaxDynamicSharedMemorySize, comb_smem);
    cudaFuncSetAttribute(apply_kernel,   cudaFuncAttributeMaxDynamicSharedMemorySize, apply_smem);

    hist_kernel<<<dim3(NBLK, 2), 256>>>(cs, ss);                        // 1
    scan_kernel<<<1, 256>>>();                                          // 2
    scatter_kernel<<<dim3(NBLK, 2), 256, scat_smem>>>(cf, sf, cs, ss);  // 3
    stats_kernel<<<dim3(MAXV, 2), 256>>>();                             // 4 (profiled)
    reduce_kernel<<<dim3(16, 4), 256>>>();                              // 5
    ns_kernel<<<16, 256, ns_smem>>>();                                  // 6
    combine_kernel<<<NL, 256, comb_smem>>>();                           // 7
    apply_kernel<<<NPIX/256, 256, apply_smem>>>();                      // 8
    writeout_kernel<<<NPIX/256, 256>>>(out);                            // 9
}